// round 2
// baseline (speedup 1.0000x reference)
#include <cuda_runtime.h>
#include <math.h>

// ---------------------------------------------------------------------------
// Problem constants
// ---------------------------------------------------------------------------
#define BATCH 512
#define MF    48      // fields
#define DD    128     // embedding dim
#define O1    68
#define O2    32
#define O3    24
#define K1TRI 1176    // 48*49/2 symmetric pairs for layer 1
#define K2    (O1*MF) // 3264
#define KT    32      // k-tile

// ---------------------------------------------------------------------------
// Device-global scratch (no allocation allowed)
// ---------------------------------------------------------------------------
__device__ float         g_wsym[K1TRI * O1];   // symmetrized w_cin1
__device__ unsigned char g_pk[K1TRI], g_pj[K1TRI];
__device__ float         g_V3[O2 * MF];        // w_cin3 folded with out_w tail
__device__ float         g_F[MF * MF * 64];    // fc1 lookup table [j][m][c]

// ---------------------------------------------------------------------------
// Prep kernels (cheap, run each launch; deterministic)
// ---------------------------------------------------------------------------
__global__ void prep_wsym(const float* __restrict__ w1) {
    int t = blockIdx.x;                 // 0..1175
    int k = 0, base = 0;
    while (t >= base + (MF - k)) { base += MF - k; ++k; }
    int j = k + (t - base);             // k <= j
    int o = threadIdx.x;                // 0..67
    float v = w1[(k * MF + j) * O1 + o];
    if (k < j) v += w1[(j * MF + k) * O1 + o];
    g_wsym[t * O1 + o] = v;
    if (o == 0) { g_pk[t] = (unsigned char)k; g_pj[t] = (unsigned char)j; }
}

__global__ void prep_V3(const float* __restrict__ w3, const float* __restrict__ out_w) {
    int n = blockIdx.x * blockDim.x + threadIdx.x;   // 0..1535
    if (n >= O2 * MF) return;
    float s = 0.f;
    #pragma unroll
    for (int o = 0; o < O3; ++o) s += w3[n * O3 + o] * out_w[25 + O1 + O2 + o];
    g_V3[n] = s;
}

__global__ void prep_F(const float* __restrict__ emb, const float* __restrict__ fc1_w) {
    __shared__ float er[DD];
    int jm = blockIdx.x;                 // j*48+m
    int m = jm % MF, j = jm / MF;
    int c = threadIdx.x;                 // 0..63
    for (int d = c; d < DD; d += 64) er[d] = emb[m * DD + d];
    __syncthreads();
    float s = 0.f;
    #pragma unroll 8
    for (int d = 0; d < DD; ++d) s += er[d] * fc1_w[(j * DD + d) * 64 + c];
    g_F[jm * 64 + c] = s;
}

// ---------------------------------------------------------------------------
// CTA-level GEMM:  C[O,128] = A[K,O]^T * P[K,128],
// where P[k,d] = U[idx_k(k), d] * V[idx_j(k), d] generated on the fly.
// ---------------------------------------------------------------------------
template<int O, int SLOTS, bool TRI>
__device__ __forceinline__ void cta_gemm(
    const float* __restrict__ Ag, int K,
    const float* __restrict__ U, const float* __restrict__ V,
    float* __restrict__ Csm, float* __restrict__ Asm, float* __restrict__ Psm,
    int tid)
{
    const int tx = tid & 31;   // column group: cols tx*4 .. tx*4+3
    const int ty = tid >> 5;   // row group: rows ty + 8*s
    float acc[SLOTS][4];
    #pragma unroll
    for (int s = 0; s < SLOTS; ++s)
        { acc[s][0] = 0.f; acc[s][1] = 0.f; acc[s][2] = 0.f; acc[s][3] = 0.f; }

    for (int k0 = 0; k0 < K; k0 += KT) {
        const int kt = min(KT, K - k0);
        __syncthreads();
        // stage A tile (coalesced from global/L2)
        for (int i = tid; i < kt * O; i += 256) Asm[i] = Ag[k0 * O + i];
        // stage P tile
        for (int i = tid; i < (kt << 7); i += 256) {
            int kk = i >> 7, d = i & 127;
            int kg = k0 + kk;
            int ks, js;
            if (TRI) { ks = (int)g_pk[kg]; js = (int)g_pj[kg]; }
            else     { ks = kg / MF;       js = kg - ks * MF; }
            Psm[i] = U[(ks << 7) + d] * V[(js << 7) + d];
        }
        __syncthreads();
        for (int kk = 0; kk < kt; ++kk) {
            const float4 pv = *(const float4*)(Psm + (kk << 7) + (tx << 2));
            const float* arow = Asm + kk * O;
            #pragma unroll
            for (int s = 0; s < SLOTS; ++s) {
                const int o = ty + (s << 3);
                if ((O & 7) && s == SLOTS - 1 && o >= O) continue;  // warp-uniform
                const float a = arow[o];
                acc[s][0] = fmaf(a, pv.x, acc[s][0]);
                acc[s][1] = fmaf(a, pv.y, acc[s][1]);
                acc[s][2] = fmaf(a, pv.z, acc[s][2]);
                acc[s][3] = fmaf(a, pv.w, acc[s][3]);
            }
        }
    }
    __syncthreads();
    #pragma unroll
    for (int s = 0; s < SLOTS; ++s) {
        const int o = ty + (s << 3);
        if (o < O) {
            float4 v; v.x = acc[s][0]; v.y = acc[s][1]; v.z = acc[s][2]; v.w = acc[s][3];
            *(float4*)(Csm + (o << 7) + (tx << 2)) = v;
        }
    }
    __syncthreads();
}

// ---------------------------------------------------------------------------
// Main fused kernel: one CTA per batch row.
// ---------------------------------------------------------------------------
// dyn smem layout (floats): x0 6144 | xk1 8704 | xk2 4096 | Asm 2176 | Psm 4096
#define SM_X0   0
#define SM_XK1  6144
#define SM_XK2  14848
#define SM_A    18944
#define SM_P    21120
#define SM_FLT  25216
#define SMEM_BYTES (SM_FLT * 4)

__global__ __launch_bounds__(256, 2) void cin_main(
    const int*   __restrict__ x,     const float* __restrict__ emb,
    const float* __restrict__ w2,
    const float* __restrict__ lin_w, const float* __restrict__ lin_b,
    const float* __restrict__ fc1_b,
    const float* __restrict__ bn1_g, const float* __restrict__ bn1_b,
    const float* __restrict__ fc2_w, const float* __restrict__ fc2_b,
    const float* __restrict__ bn2_g, const float* __restrict__ bn2_b,
    const float* __restrict__ fc3_w, const float* __restrict__ fc3_b,
    const float* __restrict__ bn3_g, const float* __restrict__ bn3_b,
    const float* __restrict__ out_w, const float* __restrict__ out_b,
    float* __restrict__ out)
{
    extern __shared__ float sm[];
    float* x0  = sm + SM_X0;
    float* xk1 = sm + SM_XK1;
    float* xk2 = sm + SM_XK2;
    float* Asm = sm + SM_A;
    float* Psm = sm + SM_P;
    __shared__ int   xr[MF];
    __shared__ float ows[152];
    __shared__ float d1s[64], d2s[48], d3s[24];
    __shared__ float red[8];

    const int tid = threadIdx.x;
    const int b   = blockIdx.x;

    if (tid < MF)  xr[tid]  = x[b * MF + tid];
    if (tid < 149) ows[tid] = out_w[tid];
    __syncthreads();

    // gather x0 = emb[x[b]]
    for (int i = tid; i < MF * DD; i += 256) {
        int j = i >> 7, d = i & 127;
        x0[i] = emb[(xr[j] << 7) + d];
    }
    // (cta_gemm begins with __syncthreads)

    // CIN layer 1 (symmetric-folded) and layer 2
    cta_gemm<O1, 9, true >(g_wsym, K1TRI, x0,  x0, xk1, Asm, Psm, tid);
    cta_gemm<O2, 4, false>(w2,     K2,    xk1, x0, xk2, Asm, Psm, tid);

    // stage V3 (reuse Asm region, 1536 <= 2176)
    for (int i = tid; i < O2 * MF; i += 256) Asm[i] = g_V3[i];
    __syncthreads();

    float part = 0.f;
    // layer-3 contribution (folded): sum_{k,d} xk2[k,d] * (V3 @ x0)[k,d]
    {
        const int tx = tid & 31, ty = tid >> 5;
        #pragma unroll
        for (int s = 0; s < 4; ++s) {
            const int r = ty + (s << 3);     // < 32
            const float* vrow = Asm + r * MF;
            float y0 = 0.f, y1 = 0.f, y2 = 0.f, y3 = 0.f;
            #pragma unroll 8
            for (int j = 0; j < MF; ++j) {
                const float v = vrow[j];
                const float4 xv = *(const float4*)(x0 + (j << 7) + (tx << 2));
                y0 = fmaf(v, xv.x, y0); y1 = fmaf(v, xv.y, y1);
                y2 = fmaf(v, xv.z, y2); y3 = fmaf(v, xv.w, y3);
            }
            const float4 kv = *(const float4*)(xk2 + (r << 7) + (tx << 2));
            part += y0 * kv.x + y1 * kv.y + y2 * kv.z + y3 * kv.w;
        }
    }
    // cin1 / cin2 sum-pools dotted with out_w
    for (int i = tid; i < O1 * DD; i += 256) part += xk1[i] * ows[25 + (i >> 7)];
    for (int i = tid; i < O2 * DD; i += 256) part += xk2[i] * ows[25 + O1 + (i >> 7)];

    // block reduce
    #pragma unroll
    for (int off = 16; off; off >>= 1) part += __shfl_xor_sync(0xffffffffu, part, off);
    if ((tid & 31) == 0) red[tid >> 5] = part;
    __syncthreads();

    // deep MLP
    const float invs = rsqrtf(1.0f + 1e-3f);
    if (tid < 64) {
        float a = fc1_b[tid];
        #pragma unroll
        for (int j = 0; j < MF; ++j) a += g_F[((j * MF + xr[j]) << 6) + tid];
        a = fmaxf(a, 0.f);
        d1s[tid] = bn1_g[tid] * a * invs + bn1_b[tid];
    }
    __syncthreads();
    if (tid < 48) {
        float a = fc2_b[tid];
        #pragma unroll 8
        for (int i = 0; i < 64; ++i) a += d1s[i] * fc2_w[i * 48 + tid];
        a = tanhf(a);
        d2s[tid] = bn2_g[tid] * a * invs + bn2_b[tid];
    }
    __syncthreads();
    if (tid < 24) {
        float a = fc3_b[tid];
        #pragma unroll 8
        for (int i = 0; i < 48; ++i) a += d2s[i] * fc3_w[i * 24 + tid];
        a = tanhf(a);
        d3s[tid] = bn3_g[tid] * a * invs + bn3_b[tid];
    }
    __syncthreads();
    if (tid == 0) {
        float lg = out_b[0];
        #pragma unroll
        for (int w = 0; w < 8; ++w) lg += red[w];
        #pragma unroll
        for (int c = 0; c < 24; ++c) lg += d3s[c] * ows[c];
        float sl = lin_b[0];
        #pragma unroll
        for (int j = 0; j < MF; ++j) sl += (float)xr[j] * lin_w[j];
        lg += tanhf(sl) * ows[24];
        out[b] = 1.0f / (1.0f + expf(-lg));
    }
}

// ---------------------------------------------------------------------------
// Launch
// ---------------------------------------------------------------------------
extern "C" void kernel_launch(void* const* d_in, const int* in_sizes, int n_in,
                              void* d_out, int out_size)
{
    const int*   x     = (const int*)  d_in[0];
    const float* emb   = (const float*)d_in[1];
    const float* w1    = (const float*)d_in[2];
    const float* w2    = (const float*)d_in[3];
    const float* w3    = (const float*)d_in[4];
    const float* lin_w = (const float*)d_in[5];
    const float* lin_b = (const float*)d_in[6];
    const float* fc1_w = (const float*)d_in[7];
    const float* fc1_b = (const float*)d_in[8];
    const float* bn1_g = (const float*)d_in[9];
    const float* bn1_b = (const float*)d_in[10];
    const float* fc2_w = (const float*)d_in[11];
    const float* fc2_b = (const float*)d_in[12];
    const float* bn2_g = (const float*)d_in[13];
    const float* bn2_b = (const float*)d_in[14];
    const float* fc3_w = (const float*)d_in[15];
    const float* fc3_b = (const float*)d_in[16];
    const float* bn3_g = (const float*)d_in[17];
    const float* bn3_b = (const float*)d_in[18];
    const float* out_w = (const float*)d_in[19];
    const float* out_b = (const float*)d_in[20];
    float* out = (float*)d_out;

    prep_wsym<<<K1TRI, O1>>>(w1);
    prep_V3<<<6, 256>>>(w3, out_w);
    prep_F<<<MF * MF, 64>>>(emb, fc1_w);

    cudaFuncSetAttribute(cin_main, cudaFuncAttributeMaxDynamicSharedMemorySize, SMEM_BYTES);
    cin_main<<<BATCH, 256, SMEM_BYTES>>>(
        x, emb, w2, lin_w, lin_b, fc1_b, bn1_g, bn1_b,
        fc2_w, fc2_b, bn2_g, bn2_b, fc3_w, fc3_b, bn3_g, bn3_b,
        out_w, out_b, out);
}